// round 3
// baseline (speedup 1.0000x reference)
#include <cuda_runtime.h>
#include <cstdint>

// ---------------------------------------------------------------------------
// Problem constants
// ---------------------------------------------------------------------------
#define SQ   1024        // sequence length S
#define NB   8           // batch B
#define ID   256         // input dim I
#define HDIM 512         // hidden H
#define NL   4           // layers L
#define NHD  8           // num heads
#define HSZ  64          // head dim
#define FFD  1024        // ffn dim
#define EPSV 1e-5f
#define NEGV (-1e9f)

// ---------------------------------------------------------------------------
// Scratch (static device globals — no runtime allocation allowed)
// ---------------------------------------------------------------------------
__device__ float g_xin[NB * SQ * ID];                     //   8 MB
__device__ float g_x[NB * SQ * HDIM];                     //  16 MB
__device__ float g_qkv[NB * SQ * 3 * HDIM];               //  48 MB
__device__ float g_scores[(size_t)NB * NHD * SQ * SQ];    // 256 MB
__device__ float g_o[NB * SQ * HDIM];                     //  16 MB
__device__ float g_ffn[NB * SQ * FFD];                    //  32 MB
__device__ float g_tmp[NB * SQ * HDIM];                   //  16 MB

// ---------------------------------------------------------------------------
// (S, B, I) -> (B, S, I)
// ---------------------------------------------------------------------------
__global__ void transpose_nodes(const float* __restrict__ nodes,
                                float* __restrict__ xin) {
    int idx = blockIdx.x * blockDim.x + threadIdx.x;
    if (idx >= NB * SQ * ID) return;
    int i  = idx % ID;
    int bs = idx / ID;
    int s  = bs % SQ;
    int b  = bs / SQ;
    xin[idx] = nodes[((size_t)s * NB + b) * ID + i];
}

// ---------------------------------------------------------------------------
// Generic TN SGEMM: C[m,n] = act( sum_k A[m,k] * W[n,k] + bias[n] )
// A: M x K row-major (lda), W: N x K row-major (ldb). 128x128x8 tile,
// 256 threads, 8x8 register tile. Requires M%128==0, N%128==0, K%8==0.
// ---------------------------------------------------------------------------
__global__ void __launch_bounds__(256)
gemm_tn(const float* __restrict__ A, int lda,
        const float* __restrict__ W, int ldb,
        const float* __restrict__ bias,
        float* __restrict__ C, int ldc,
        int K, int relu) {
    __shared__ float As[8][128];
    __shared__ float Bs[8][128];

    const int tid = threadIdx.x;
    const int bm = blockIdx.y * 128;
    const int bn = blockIdx.x * 128;

    const int lrow = tid >> 1;          // 0..127
    const int lcol = (tid & 1) * 4;     // 0 or 4
    const int trow = (tid >> 4) * 8;    // 0..120
    const int tcol = (tid & 15) * 8;    // 0..120

    const float* Ap = A + (size_t)(bm + lrow) * lda + lcol;
    const float* Wp = W + (size_t)(bn + lrow) * ldb + lcol;

    float acc[8][8];
#pragma unroll
    for (int i = 0; i < 8; i++)
#pragma unroll
        for (int j = 0; j < 8; j++) acc[i][j] = 0.f;

    for (int k0 = 0; k0 < K; k0 += 8) {
        float4 av = *(const float4*)(Ap + k0);
        float4 bv = *(const float4*)(Wp + k0);
        As[lcol + 0][lrow] = av.x;
        As[lcol + 1][lrow] = av.y;
        As[lcol + 2][lrow] = av.z;
        As[lcol + 3][lrow] = av.w;
        Bs[lcol + 0][lrow] = bv.x;
        Bs[lcol + 1][lrow] = bv.y;
        Bs[lcol + 2][lrow] = bv.z;
        Bs[lcol + 3][lrow] = bv.w;
        __syncthreads();
#pragma unroll
        for (int kk = 0; kk < 8; kk++) {
            float a[8], b[8];
#pragma unroll
            for (int i = 0; i < 8; i++) a[i] = As[kk][trow + i];
#pragma unroll
            for (int j = 0; j < 8; j++) b[j] = Bs[kk][tcol + j];
#pragma unroll
            for (int i = 0; i < 8; i++)
#pragma unroll
                for (int j = 0; j < 8; j++) acc[i][j] = fmaf(a[i], b[j], acc[i][j]);
        }
        __syncthreads();
    }

#pragma unroll
    for (int i = 0; i < 8; i++) {
        float* crow = C + (size_t)(bm + trow + i) * ldc + bn + tcol;
#pragma unroll
        for (int j = 0; j < 8; j++) {
            float v = acc[i][j] + bias[bn + tcol + j];
            if (relu) v = fmaxf(v, 0.f);
            crow[j] = v;
        }
    }
}

// ---------------------------------------------------------------------------
// Attention scores: per (b,h) batch of S x S = Q @ K^T * scale + mask bias.
// Q[m,k] = qkv[(b*S+m)*3H + h*64 + k]; K[n,k] = qkv[(b*S+n)*3H + H + h*64 + k]
// ---------------------------------------------------------------------------
__global__ void __launch_bounds__(256)
scores_gemm(const float* __restrict__ qkv, const int* __restrict__ dist,
            float* __restrict__ scores) {
    __shared__ float As[8][128];
    __shared__ float Bs[8][128];

    const int bz = blockIdx.z;
    const int b = bz >> 3;
    const int h = bz & 7;
    const float* A = qkv + (size_t)b * SQ * (3 * HDIM) + h * HSZ;          // Q
    const float* W = qkv + (size_t)b * SQ * (3 * HDIM) + HDIM + h * HSZ;   // K
    float* C = scores + (size_t)bz * SQ * SQ;

    const int tid = threadIdx.x;
    const int bm = blockIdx.y * 128;
    const int bn = blockIdx.x * 128;

    const int lrow = tid >> 1;
    const int lcol = (tid & 1) * 4;
    const int trow = (tid >> 4) * 8;
    const int tcol = (tid & 15) * 8;

    const float* Ap = A + (size_t)(bm + lrow) * (3 * HDIM) + lcol;
    const float* Wp = W + (size_t)(bn + lrow) * (3 * HDIM) + lcol;

    float acc[8][8];
#pragma unroll
    for (int i = 0; i < 8; i++)
#pragma unroll
        for (int j = 0; j < 8; j++) acc[i][j] = 0.f;

    for (int k0 = 0; k0 < HSZ; k0 += 8) {
        float4 av = *(const float4*)(Ap + k0);
        float4 bv = *(const float4*)(Wp + k0);
        As[lcol + 0][lrow] = av.x;
        As[lcol + 1][lrow] = av.y;
        As[lcol + 2][lrow] = av.z;
        As[lcol + 3][lrow] = av.w;
        Bs[lcol + 0][lrow] = bv.x;
        Bs[lcol + 1][lrow] = bv.y;
        Bs[lcol + 2][lrow] = bv.z;
        Bs[lcol + 3][lrow] = bv.w;
        __syncthreads();
#pragma unroll
        for (int kk = 0; kk < 8; kk++) {
            float a[8], bb[8];
#pragma unroll
            for (int i = 0; i < 8; i++) a[i] = As[kk][trow + i];
#pragma unroll
            for (int j = 0; j < 8; j++) bb[j] = Bs[kk][tcol + j];
#pragma unroll
            for (int i = 0; i < 8; i++)
#pragma unroll
                for (int j = 0; j < 8; j++) acc[i][j] = fmaf(a[i], bb[j], acc[i][j]);
        }
        __syncthreads();
    }

    const int* dbase = dist + (size_t)b * SQ * SQ;  // dist[b, q, k]
#pragma unroll
    for (int i = 0; i < 8; i++) {
        const int m = bm + trow + i;
        const int* drow = dbase + (size_t)m * SQ;
#pragma unroll
        for (int j = 0; j < 8; j++) {
            const int n = bn + tcol + j;
            int d = (h < 6) ? drow[n] : dbase[n];   // global heads use dist[b,0,n]
            bool allowed = (m == n);
            if (h < 4) allowed = allowed || (d == 1);    // short heads
            else       allowed = allowed || (d >= 1);    // long + global heads
            C[(size_t)m * SQ + n] = acc[i][j] * 0.125f + (allowed ? 0.f : NEGV);
        }
    }
}

// ---------------------------------------------------------------------------
// Row softmax over S=1024 columns. One block (256 threads) per row.
// ---------------------------------------------------------------------------
__global__ void __launch_bounds__(256)
softmax_rows(float* __restrict__ s) {
    __shared__ float red[256];
    const int t = threadIdx.x;
    float* p = s + (size_t)blockIdx.x * SQ;

    float4 v = *(float4*)(p + t * 4);
    float mx = fmaxf(fmaxf(v.x, v.y), fmaxf(v.z, v.w));
    red[t] = mx;
    __syncthreads();
    for (int off = 128; off > 0; off >>= 1) {
        if (t < off) red[t] = fmaxf(red[t], red[t + off]);
        __syncthreads();
    }
    mx = red[0];
    __syncthreads();

    v.x = __expf(v.x - mx);
    v.y = __expf(v.y - mx);
    v.z = __expf(v.z - mx);
    v.w = __expf(v.w - mx);
    red[t] = v.x + v.y + v.z + v.w;
    __syncthreads();
    for (int off = 128; off > 0; off >>= 1) {
        if (t < off) red[t] += red[t + off];
        __syncthreads();
    }
    const float inv = 1.f / red[0];
    v.x *= inv; v.y *= inv; v.z *= inv; v.w *= inv;
    *(float4*)(p + t * 4) = v;
}

// ---------------------------------------------------------------------------
// AV GEMM: O[b,m,h,:] = attn[b,h,m,:] @ V[b,h,:,:]. 64x64x32 tile per block.
// grid: (S/64, B*NH)
// ---------------------------------------------------------------------------
__global__ void __launch_bounds__(256)
av_gemm(const float* __restrict__ scores, const float* __restrict__ qkv,
        float* __restrict__ o) {
    __shared__ float As[32][65];  // [k][m], padded
    __shared__ float Bs[32][64];  // [k][d]

    const int bz = blockIdx.y;
    const int b = bz >> 3;
    const int h = bz & 7;
    const int bm = blockIdx.x * 64;

    const float* A = scores + (size_t)bz * SQ * SQ;                        // attn
    const float* V = qkv + (size_t)b * SQ * (3 * HDIM) + 2 * HDIM + h * HSZ;
    float* C = o + (size_t)b * SQ * HDIM + h * HSZ;

    const int tid = threadIdx.x;
    const int ar = tid >> 3;           // 0..31
    const int ac = (tid & 7) * 4;      // 0..28
    const int br = tid >> 4;           // 0..15
    const int bc = (tid & 15) * 4;     // 0..60
    const int trow = (tid >> 4) * 4;
    const int tcol = (tid & 15) * 4;

    float acc[4][4];
#pragma unroll
    for (int i = 0; i < 4; i++)
#pragma unroll
        for (int j = 0; j < 4; j++) acc[i][j] = 0.f;

    for (int k0 = 0; k0 < SQ; k0 += 32) {
#pragma unroll
        for (int r = 0; r < 2; r++) {
            const int row = ar + r * 32;
            float4 av = *(const float4*)(A + (size_t)(bm + row) * SQ + k0 + ac);
            As[ac + 0][row] = av.x;
            As[ac + 1][row] = av.y;
            As[ac + 2][row] = av.z;
            As[ac + 3][row] = av.w;
            const int krow = br + r * 16;
            float4 bv = *(const float4*)(V + (size_t)(k0 + krow) * (3 * HDIM) + bc);
            *(float4*)&Bs[krow][bc] = bv;
        }
        __syncthreads();
#pragma unroll
        for (int kk = 0; kk < 32; kk++) {
            float a[4], bb[4];
#pragma unroll
            for (int i = 0; i < 4; i++) a[i] = As[kk][trow + i];
#pragma unroll
            for (int j = 0; j < 4; j++) bb[j] = Bs[kk][tcol + j];
#pragma unroll
            for (int i = 0; i < 4; i++)
#pragma unroll
                for (int j = 0; j < 4; j++) acc[i][j] = fmaf(a[i], bb[j], acc[i][j]);
        }
        __syncthreads();
    }

#pragma unroll
    for (int i = 0; i < 4; i++)
#pragma unroll
        for (int j = 0; j < 4; j++)
            C[(size_t)(bm + trow + i) * HDIM + tcol + j] = acc[i][j];
}

// ---------------------------------------------------------------------------
// LayerNorm over H=512, optional residual add. One block (256 thr) per row.
// out = LN(y [+ res]) * g + b. Safe when out/res alias (row fully read first).
// ---------------------------------------------------------------------------
__global__ void __launch_bounds__(256)
ln_kernel(const float* __restrict__ y, const float* __restrict__ res,
          const float* __restrict__ g, const float* __restrict__ bta,
          float* __restrict__ out) {
    __shared__ float red[256];
    const int t = threadIdx.x;
    const size_t base = (size_t)blockIdx.x * HDIM;

    float v0 = y[base + t];
    float v1 = y[base + t + 256];
    if (res) {
        v0 += res[base + t];
        v1 += res[base + t + 256];
    }

    red[t] = v0 + v1;
    __syncthreads();
    for (int off = 128; off > 0; off >>= 1) {
        if (t < off) red[t] += red[t + off];
        __syncthreads();
    }
    const float mean = red[0] * (1.f / HDIM);
    __syncthreads();

    const float d0 = v0 - mean, d1 = v1 - mean;
    red[t] = d0 * d0 + d1 * d1;
    __syncthreads();
    for (int off = 128; off > 0; off >>= 1) {
        if (t < off) red[t] += red[t + off];
        __syncthreads();
    }
    const float r = rsqrtf(red[0] * (1.f / HDIM) + EPSV);

    out[base + t]       = d0 * r * g[t] + bta[t];
    out[base + t + 256] = d1 * r * g[t + 256] + bta[t + 256];
}

// ---------------------------------------------------------------------------
// Final batch-norm over B=8 samples of x[:,0,:]. out[b,h].
// ---------------------------------------------------------------------------
__global__ void bn_kernel(const float* __restrict__ x, const float* __restrict__ g,
                          const float* __restrict__ bb, float* __restrict__ out) {
    const int h = blockIdx.x * blockDim.x + threadIdx.x;
    if (h >= HDIM) return;
    float v[NB];
    float m = 0.f;
#pragma unroll
    for (int b = 0; b < NB; b++) {
        v[b] = x[(size_t)b * SQ * HDIM + h];
        m += v[b];
    }
    m *= (1.f / NB);
    float var = 0.f;
#pragma unroll
    for (int b = 0; b < NB; b++) {
        float d = v[b] - m;
        var += d * d;
    }
    var *= (1.f / NB);
    const float r = rsqrtf(var + EPSV);
#pragma unroll
    for (int b = 0; b < NB; b++)
        out[b * HDIM + h] = (v[b] - m) * r * g[h] + bb[h];
}

// ---------------------------------------------------------------------------
// Launch
// ---------------------------------------------------------------------------
extern "C" void kernel_launch(void* const* d_in, const int* in_sizes, int n_in,
                              void* d_out, int out_size) {
    (void)in_sizes; (void)n_in; (void)out_size;

    const float* nodes      = (const float*)d_in[0];
    const int*   dist       = (const int*)d_in[1];
    const float* dense_w    = (const float*)d_in[2];
    const float* dense_b    = (const float*)d_in[3];
    const float* dense_ln_g = (const float*)d_in[4];
    const float* dense_ln_b = (const float*)d_in[5];
    const float* qkv_w      = (const float*)d_in[6];
    const float* qkv_b      = (const float*)d_in[7];
    const float* out_w      = (const float*)d_in[8];
    const float* out_b      = (const float*)d_in[9];
    const float* ln1_g      = (const float*)d_in[10];
    const float* ln1_b      = (const float*)d_in[11];
    const float* ffn_w1     = (const float*)d_in[12];
    const float* ffn_b1     = (const float*)d_in[13];
    const float* ffn_w2     = (const float*)d_in[14];
    const float* ffn_b2     = (const float*)d_in[15];
    const float* ln2_g      = (const float*)d_in[16];
    const float* ln2_b      = (const float*)d_in[17];
    const float* bn_g       = (const float*)d_in[18];
    const float* bn_b       = (const float*)d_in[19];
    float* out = (float*)d_out;

    float *xin, *x, *qkv, *scores, *o, *ffn, *tmp;
    cudaGetSymbolAddress((void**)&xin,    g_xin);
    cudaGetSymbolAddress((void**)&x,      g_x);
    cudaGetSymbolAddress((void**)&qkv,    g_qkv);
    cudaGetSymbolAddress((void**)&scores, g_scores);
    cudaGetSymbolAddress((void**)&o,      g_o);
    cudaGetSymbolAddress((void**)&ffn,    g_ffn);
    cudaGetSymbolAddress((void**)&tmp,    g_tmp);

    const int M = NB * SQ;  // 8192 rows

    // input transpose + dense projection + LN
    transpose_nodes<<<(NB * SQ * ID + 255) / 256, 256>>>(nodes, xin);
    gemm_tn<<<dim3(HDIM / 128, M / 128), 256>>>(xin, ID, dense_w, ID, dense_b,
                                                tmp, HDIM, ID, 0);
    ln_kernel<<<M, 256>>>(tmp, nullptr, dense_ln_g, dense_ln_b, x);

    for (int l = 0; l < NL; l++) {
        // QKV projection: [8192,512] @ [1536,512]^T
        gemm_tn<<<dim3(3 * HDIM / 128, M / 128), 256>>>(
            x, HDIM, qkv_w + (size_t)l * 3 * HDIM * HDIM, HDIM,
            qkv_b + l * 3 * HDIM, qkv, 3 * HDIM, HDIM, 0);

        // scores = QK^T * scale + mask-bias (fused), per (b,h)
        scores_gemm<<<dim3(SQ / 128, SQ / 128, NB * NHD), 256>>>(qkv, dist, scores);

        // softmax rows
        softmax_rows<<<NB * NHD * SQ, 256>>>(scores);

        // O = attn @ V
        av_gemm<<<dim3(SQ / 64, NB * NHD), 256>>>(scores, qkv, o);

        // output projection + residual LN
        gemm_tn<<<dim3(HDIM / 128, M / 128), 256>>>(
            o, HDIM, out_w + (size_t)l * HDIM * HDIM, HDIM,
            out_b + l * HDIM, tmp, HDIM, HDIM, 0);
        ln_kernel<<<M, 256>>>(tmp, x, ln1_g + l * HDIM, ln1_b + l * HDIM, x);

        // FFN
        gemm_tn<<<dim3(FFD / 128, M / 128), 256>>>(
            x, HDIM, ffn_w1 + (size_t)l * FFD * HDIM, HDIM,
            ffn_b1 + l * FFD, ffn, FFD, HDIM, 1);
        gemm_tn<<<dim3(HDIM / 128, M / 128), 256>>>(
            ffn, FFD, ffn_w2 + (size_t)l * HDIM * FFD, FFD,
            ffn_b2 + l * HDIM, tmp, HDIM, FFD, 0);
        ln_kernel<<<M, 256>>>(tmp, x, ln2_g + l * HDIM, ln2_b + l * HDIM, x);
    }

    // final batch-norm over batch dim of x[:, 0, :]
    bn_kernel<<<1, HDIM>>>(x, bn_g, bn_b, out);
}

// round 6
// speedup vs baseline: 2.1624x; 2.1624x over previous
#include <cuda_runtime.h>
#include <cstdint>

// ---------------------------------------------------------------------------
// Problem constants
// ---------------------------------------------------------------------------
#define SQ   1024        // sequence length S
#define NB   8           // batch B
#define ID   256         // input dim I
#define HDIM 512         // hidden H
#define NL   4           // layers L
#define NHD  8           // num heads
#define HSZ  64          // head dim
#define FFD  1024        // ffn dim
#define EPSV 1e-5f
#define NEGV (-1e9f)

#define KT   16          // K tile
#define ASTR 20          // smem row stride (16 + 4 pad) -> conflict-free frag reads
#define BSTR 72          // AV V-tile row stride (64 + 8 pad)

// ---------------------------------------------------------------------------
// Scratch (static device globals — no runtime allocation allowed)
// ---------------------------------------------------------------------------
__device__ float g_xin[NB * SQ * ID];
__device__ float g_x[NB * SQ * HDIM];
__device__ float g_qkv[NB * SQ * 3 * HDIM];
__device__ float g_scores[(size_t)NB * NHD * SQ * SQ];
__device__ float g_o[NB * SQ * HDIM];
__device__ float g_ffn[NB * SQ * FFD];
__device__ float g_tmp[NB * SQ * HDIM];

// ---------------------------------------------------------------------------
// TF32 helpers
// ---------------------------------------------------------------------------
__device__ __forceinline__ float to_tf32(float x) {
    uint32_t u;
    asm("cvt.rna.tf32.f32 %0, %1;" : "=r"(u) : "f"(x));
    return __uint_as_float(u);
}

__device__ __forceinline__ void st_tf32(float* p, float4 v) {
    p[0] = to_tf32(v.x); p[1] = to_tf32(v.y);
    p[2] = to_tf32(v.z); p[3] = to_tf32(v.w);
}

__device__ __forceinline__ void mma_tf32(float* d, const uint32_t* a, const uint32_t* b) {
    asm volatile(
        "mma.sync.aligned.m16n8k8.row.col.f32.tf32.tf32.f32 "
        "{%0,%1,%2,%3}, {%4,%5,%6,%7}, {%8,%9}, {%0,%1,%2,%3};\n"
        : "+f"(d[0]), "+f"(d[1]), "+f"(d[2]), "+f"(d[3])
        : "r"(a[0]), "r"(a[1]), "r"(a[2]), "r"(a[3]), "r"(b[0]), "r"(b[1]));
}

// ---------------------------------------------------------------------------
// (S, B, I) -> (B, S, I)
// ---------------------------------------------------------------------------
__global__ void transpose_nodes(const float* __restrict__ nodes,
                                float* __restrict__ xin) {
    int idx = blockIdx.x * blockDim.x + threadIdx.x;
    if (idx >= NB * SQ * ID) return;
    int i  = idx % ID;
    int bs = idx / ID;
    int s  = bs % SQ;
    int b  = bs / SQ;
    xin[idx] = nodes[((size_t)s * NB + b) * ID + i];
}

// ---------------------------------------------------------------------------
// TF32 TN GEMM: C[m,n] = act( sum_k A[m,k] * W[n,k] + bias[n] )
// Block 128x128xKT, 8 warps (2M x 4N), warp tile 64x32, m16n8k8 MMA,
// double-buffered smem. Requires M%128==0, N%128==0, K%16==0.
// ---------------------------------------------------------------------------
__global__ void __launch_bounds__(256)
gemm_tn_tf32(const float* __restrict__ A, int lda,
             const float* __restrict__ W, int ldb,
             const float* __restrict__ bias,
             float* __restrict__ C, int ldc,
             int K, int relu) {
    __shared__ float As[2][128][ASTR];
    __shared__ float Bs[2][128][ASTR];

    const int tid = threadIdx.x;
    const int bm = blockIdx.y * 128, bn = blockIdx.x * 128;
    const int r = tid >> 2, c4 = (tid & 3) * 4;
    const int wid = tid >> 5, lane = tid & 31;
    const int wm = (wid & 1) * 64, wn = (wid >> 1) * 32;
    const int g = lane >> 2, tig = lane & 3;

    const float* Ap0 = A + (size_t)(bm + r) * lda + c4;
    const float* Ap1 = Ap0 + (size_t)64 * lda;
    const float* Wp0 = W + (size_t)(bn + r) * ldb + c4;
    const float* Wp1 = Wp0 + (size_t)64 * ldb;

    float acc[4][4][4];
#pragma unroll
    for (int mi = 0; mi < 4; mi++)
#pragma unroll
        for (int ni = 0; ni < 4; ni++)
#pragma unroll
            for (int c = 0; c < 4; c++) acc[mi][ni][c] = 0.f;

    float4 av0 = *(const float4*)Ap0;
    float4 av1 = *(const float4*)Ap1;
    float4 bv0 = *(const float4*)Wp0;
    float4 bv1 = *(const float4*)Wp1;
    st_tf32(&As[0][r][c4], av0);
    st_tf32(&As[0][r + 64][c4], av1);
    st_tf32(&Bs[0][r][c4], bv0);
    st_tf32(&Bs[0][r + 64][c4], bv1);
    __syncthreads();

    const int nt = K / KT;
    for (int t = 0; t < nt; t++) {
        const int buf = t & 1;
        if (t + 1 < nt) {
            const int ko = (t + 1) * KT;
            av0 = *(const float4*)(Ap0 + ko);
            av1 = *(const float4*)(Ap1 + ko);
            bv0 = *(const float4*)(Wp0 + ko);
            bv1 = *(const float4*)(Wp1 + ko);
        }
#pragma unroll
        for (int kk = 0; kk < KT; kk += 8) {
            uint32_t af[4][4], bf[4][2];
#pragma unroll
            for (int mi = 0; mi < 4; mi++) {
                const int row = wm + mi * 16 + g;
                af[mi][0] = __float_as_uint(As[buf][row][kk + tig]);
                af[mi][1] = __float_as_uint(As[buf][row + 8][kk + tig]);
                af[mi][2] = __float_as_uint(As[buf][row][kk + tig + 4]);
                af[mi][3] = __float_as_uint(As[buf][row + 8][kk + tig + 4]);
            }
#pragma unroll
            for (int ni = 0; ni < 4; ni++) {
                const int col = wn + ni * 8 + g;
                bf[ni][0] = __float_as_uint(Bs[buf][col][kk + tig]);
                bf[ni][1] = __float_as_uint(Bs[buf][col][kk + tig + 4]);
            }
#pragma unroll
            for (int mi = 0; mi < 4; mi++)
#pragma unroll
                for (int ni = 0; ni < 4; ni++)
                    mma_tf32(acc[mi][ni], af[mi], bf[ni]);
        }
        if (t + 1 < nt) {
            const int nb = buf ^ 1;
            st_tf32(&As[nb][r][c4], av0);
            st_tf32(&As[nb][r + 64][c4], av1);
            st_tf32(&Bs[nb][r][c4], bv0);
            st_tf32(&Bs[nb][r + 64][c4], bv1);
        }
        __syncthreads();
    }

#pragma unroll
    for (int mi = 0; mi < 4; mi++) {
        const int row0 = bm + wm + mi * 16 + g;
        const int row1 = row0 + 8;
#pragma unroll
        for (int ni = 0; ni < 4; ni++) {
            const int col = bn + wn + ni * 8 + 2 * tig;
            const float b0 = bias[col], b1 = bias[col + 1];
            float v0 = acc[mi][ni][0] + b0;
            float v1 = acc[mi][ni][1] + b1;
            float v2 = acc[mi][ni][2] + b0;
            float v3 = acc[mi][ni][3] + b1;
            if (relu) {
                v0 = fmaxf(v0, 0.f); v1 = fmaxf(v1, 0.f);
                v2 = fmaxf(v2, 0.f); v3 = fmaxf(v3, 0.f);
            }
            *(float2*)(C + (size_t)row0 * ldc + col) = make_float2(v0, v1);
            *(float2*)(C + (size_t)row1 * ldc + col) = make_float2(v2, v3);
        }
    }
}

// ---------------------------------------------------------------------------
// Attention scores (TF32 MMA): per (b,h), S x S = Q @ K^T * 0.125 + mask bias
// ---------------------------------------------------------------------------
__global__ void __launch_bounds__(256)
scores_gemm_tf32(const float* __restrict__ qkv, const int* __restrict__ dist,
                 float* __restrict__ scores) {
    __shared__ float As[2][128][ASTR];
    __shared__ float Bs[2][128][ASTR];

    const int bz = blockIdx.z;
    const int b = bz >> 3;
    const int h = bz & 7;
    const float* A = qkv + (size_t)b * SQ * (3 * HDIM) + h * HSZ;          // Q
    const float* W = qkv + (size_t)b * SQ * (3 * HDIM) + HDIM + h * HSZ;   // K
    float* C = scores + (size_t)bz * SQ * SQ;
    const int* dbase = dist + (size_t)b * SQ * SQ;

    const int tid = threadIdx.x;
    const int bm = blockIdx.y * 128, bn = blockIdx.x * 128;
    const int r = tid >> 2, c4 = (tid & 3) * 4;
    const int wid = tid >> 5, lane = tid & 31;
    const int wm = (wid & 1) * 64, wn = (wid >> 1) * 32;
    const int g = lane >> 2, tig = lane & 3;

    const float* Ap0 = A + (size_t)(bm + r) * (3 * HDIM) + c4;
    const float* Ap1 = Ap0 + (size_t)64 * (3 * HDIM);
    const float* Wp0 = W + (size_t)(bn + r) * (3 * HDIM) + c4;
    const float* Wp1 = Wp0 + (size_t)64 * (3 * HDIM);

    float acc[4][4][4];
#pragma unroll
    for (int mi = 0; mi < 4; mi++)
#pragma unroll
        for (int ni = 0; ni < 4; ni++)
#pragma unroll
            for (int c = 0; c < 4; c++) acc[mi][ni][c] = 0.f;

    float4 av0 = *(const float4*)Ap0;
    float4 av1 = *(const float4*)Ap1;
    float4 bv0 = *(const float4*)Wp0;
    float4 bv1 = *(const float4*)Wp1;
    st_tf32(&As[0][r][c4], av0);
    st_tf32(&As[0][r + 64][c4], av1);
    st_tf32(&Bs[0][r][c4], bv0);
    st_tf32(&Bs[0][r + 64][c4], bv1);
    __syncthreads();

    const int nt = HSZ / KT;  // 4
#pragma unroll
    for (int t = 0; t < nt; t++) {
        const int buf = t & 1;
        if (t + 1 < nt) {
            const int ko = (t + 1) * KT;
            av0 = *(const float4*)(Ap0 + ko);
            av1 = *(const float4*)(Ap1 + ko);
            bv0 = *(const float4*)(Wp0 + ko);
            bv1 = *(const float4*)(Wp1 + ko);
        }
#pragma unroll
        for (int kk = 0; kk < KT; kk += 8) {
            uint32_t af[4][4], bf[4][2];
#pragma unroll
            for (int mi = 0; mi < 4; mi++) {
                const int row = wm + mi * 16 + g;
                af[mi][0] = __float_as_uint(As[buf][row][kk + tig]);
                af[mi][1] = __float_as_uint(As[buf][row + 8][kk + tig]);
                af[mi][2] = __float_as_uint(As[buf][row][kk + tig + 4]);
                af[mi][3] = __float_as_uint(As[buf][row + 8][kk + tig + 4]);
            }
#pragma unroll
            for (int ni = 0; ni < 4; ni++) {
                const int col = wn + ni * 8 + g;
                bf[ni][0] = __float_as_uint(Bs[buf][col][kk + tig]);
                bf[ni][1] = __float_as_uint(Bs[buf][col][kk + tig + 4]);
            }
#pragma unroll
            for (int mi = 0; mi < 4; mi++)
#pragma unroll
                for (int ni = 0; ni < 4; ni++)
                    mma_tf32(acc[mi][ni], af[mi], bf[ni]);
        }
        if (t + 1 < nt) {
            const int nb = buf ^ 1;
            st_tf32(&As[nb][r][c4], av0);
            st_tf32(&As[nb][r + 64][c4], av1);
            st_tf32(&Bs[nb][r][c4], bv0);
            st_tf32(&Bs[nb][r + 64][c4], bv1);
        }
        __syncthreads();
    }

    const bool row_head = (h < 6);   // short+long use dist[b,q,k]; global dist[b,0,k]
    const bool shorth   = (h < 4);
#pragma unroll
    for (int mi = 0; mi < 4; mi++) {
        const int row0 = bm + wm + mi * 16 + g;
        const int row1 = row0 + 8;
        const int* dr0 = dbase + (size_t)row0 * SQ;
        const int* dr1 = dbase + (size_t)row1 * SQ;
#pragma unroll
        for (int ni = 0; ni < 4; ni++) {
            const int col = bn + wn + ni * 8 + 2 * tig;
            const int d00 = row_head ? dr0[col]     : dbase[col];
            const int d01 = row_head ? dr0[col + 1] : dbase[col + 1];
            const int d10 = row_head ? dr1[col]     : dbase[col];
            const int d11 = row_head ? dr1[col + 1] : dbase[col + 1];
            bool a00 = (row0 == col)     || (shorth ? (d00 == 1) : (d00 >= 1));
            bool a01 = (row0 == col + 1) || (shorth ? (d01 == 1) : (d01 >= 1));
            bool a10 = (row1 == col)     || (shorth ? (d10 == 1) : (d10 >= 1));
            bool a11 = (row1 == col + 1) || (shorth ? (d11 == 1) : (d11 >= 1));
            float v0 = acc[mi][ni][0] * 0.125f + (a00 ? 0.f : NEGV);
            float v1 = acc[mi][ni][1] * 0.125f + (a01 ? 0.f : NEGV);
            float v2 = acc[mi][ni][2] * 0.125f + (a10 ? 0.f : NEGV);
            float v3 = acc[mi][ni][3] * 0.125f + (a11 ? 0.f : NEGV);
            *(float2*)(C + (size_t)row0 * SQ + col) = make_float2(v0, v1);
            *(float2*)(C + (size_t)row1 * SQ + col) = make_float2(v2, v3);
        }
    }
}

// ---------------------------------------------------------------------------
// Row softmax over S=1024 columns. One block (256 threads) per row.
// ---------------------------------------------------------------------------
__global__ void __launch_bounds__(256)
softmax_rows(float* __restrict__ s) {
    __shared__ float red[256];
    const int t = threadIdx.x;
    float* p = s + (size_t)blockIdx.x * SQ;

    float4 v = *(float4*)(p + t * 4);
    float mx = fmaxf(fmaxf(v.x, v.y), fmaxf(v.z, v.w));
    red[t] = mx;
    __syncthreads();
    for (int off = 128; off > 0; off >>= 1) {
        if (t < off) red[t] = fmaxf(red[t], red[t + off]);
        __syncthreads();
    }
    mx = red[0];
    __syncthreads();

    v.x = __expf(v.x - mx);
    v.y = __expf(v.y - mx);
    v.z = __expf(v.z - mx);
    v.w = __expf(v.w - mx);
    red[t] = v.x + v.y + v.z + v.w;
    __syncthreads();
    for (int off = 128; off > 0; off >>= 1) {
        if (t < off) red[t] += red[t + off];
        __syncthreads();
    }
    const float inv = 1.f / red[0];
    v.x *= inv; v.y *= inv; v.z *= inv; v.w *= inv;
    *(float4*)(p + t * 4) = v;
}

// ---------------------------------------------------------------------------
// AV GEMM (TF32 MMA): O[b,m,h*64:] = attn[b,h,m,:] @ V[b,h,:,:]
// Block 128(M) x 64(N) x 16(K), 8 warps (2M x 4N), warp tile 64x16.
// ---------------------------------------------------------------------------
__global__ void __launch_bounds__(256)
av_gemm_tf32(const float* __restrict__ scores, const float* __restrict__ qkv,
             float* __restrict__ o) {
    __shared__ float As[2][128][ASTR];
    __shared__ float Bs[2][KT][BSTR];

    const int bz = blockIdx.y;
    const int b = bz >> 3;
    const int h = bz & 7;
    const int bm = blockIdx.x * 128;

    const float* A = scores + (size_t)bz * SQ * SQ;                         // attn
    const float* V = qkv + (size_t)b * SQ * (3 * HDIM) + 2 * HDIM + h * HSZ;
    float* C = o + (size_t)b * SQ * HDIM + h * HSZ;

    const int tid = threadIdx.x;
    const int r = tid >> 2, c4 = (tid & 3) * 4;       // A loader: 64 rows x 16 cols x2
    const int kb = tid >> 4, n4 = (tid & 15) * 4;     // B loader: 16 rows x 64 cols
    const int wid = tid >> 5, lane = tid & 31;
    const int wm = (wid & 1) * 64, wn = (wid >> 1) * 16;
    const int g = lane >> 2, tig = lane & 3;

    const float* Ap0 = A + (size_t)(bm + r) * SQ + c4;
    const float* Ap1 = Ap0 + (size_t)64 * SQ;
    const float* Vp  = V + (size_t)kb * (3 * HDIM) + n4;

    float acc[4][2][4];
#pragma unroll
    for (int mi = 0; mi < 4; mi++)
#pragma unroll
        for (int ni = 0; ni < 2; ni++)
#pragma unroll
            for (int c = 0; c < 4; c++) acc[mi][ni][c] = 0.f;

    float4 av0 = *(const float4*)Ap0;
    float4 av1 = *(const float4*)Ap1;
    float4 bv  = *(const float4*)Vp;
    st_tf32(&As[0][r][c4], av0);
    st_tf32(&As[0][r + 64][c4], av1);
    st_tf32(&Bs[0][kb][n4], bv);
    __syncthreads();

    const int nt = SQ / KT;  // 64
    for (int t = 0; t < nt; t++) {
        const int buf = t & 1;
        if (t + 1 < nt) {
            av0 = *(const float4*)(Ap0 + (t + 1) * KT);
            av1 = *(const float4*)(Ap1 + (t + 1) * KT);
            bv  = *(const float4*)(Vp + (size_t)(t + 1) * KT * (3 * HDIM));
        }
#pragma unroll
        for (int kk = 0; kk < KT; kk += 8) {
            uint32_t af[4][4], bf[2][2];
#pragma unroll
            for (int mi = 0; mi < 4; mi++) {
                const int row = wm + mi * 16 + g;
                af[mi][0] = __float_as_uint(As[buf][row][kk + tig]);
                af[mi][1] = __float_as_uint(As[buf][row + 8][kk + tig]);
                af[mi][2] = __float_as_uint(As[buf][row][kk + tig + 4]);
                af[mi][3] = __float_as_uint(As[buf][row + 8][kk + tig + 4]);
            }
#pragma unroll
            for (int ni = 0; ni < 2; ni++) {
                const int col = wn + ni * 8 + g;
                bf[ni][0] = __float_as_uint(Bs[buf][kk + tig][col]);
                bf[ni][1] = __float_as_uint(Bs[buf][kk + tig + 4][col]);
            }
#pragma unroll
            for (int mi = 0; mi < 4; mi++)
#pragma unroll
                for (int ni = 0; ni < 2; ni++)
                    mma_tf32(acc[mi][ni], af[mi], bf[ni]);
        }
        if (t + 1 < nt) {
            const int nb = buf ^ 1;
            st_tf32(&As[nb][r][c4], av0);
            st_tf32(&As[nb][r + 64][c4], av1);
            st_tf32(&Bs[nb][kb][n4], bv);
        }
        __syncthreads();
    }

#pragma unroll
    for (int mi = 0; mi < 4; mi++) {
        const int row0 = bm + wm + mi * 16 + g;
        const int row1 = row0 + 8;
#pragma unroll
        for (int ni = 0; ni < 2; ni++) {
            const int col = wn + ni * 8 + 2 * tig;
            *(float2*)(C + (size_t)row0 * HDIM + col) =
                make_float2(acc[mi][ni][0], acc[mi][ni][1]);
            *(float2*)(C + (size_t)row1 * HDIM + col) =
                make_float2(acc[mi][ni][2], acc[mi][ni][3]);
        }
    }
}

// ---------------------------------------------------------------------------
// LayerNorm over H=512, optional residual add. One block (256 thr) per row.
// ---------------------------------------------------------------------------
__global__ void __launch_bounds__(256)
ln_kernel(const float* __restrict__ y, const float* __restrict__ res,
          const float* __restrict__ g, const float* __restrict__ bta,
          float* __restrict__ out) {
    __shared__ float red[256];
    const int t = threadIdx.x;
    const size_t base = (size_t)blockIdx.x * HDIM;

    float v0 = y[base + t];
    float v1 = y[base + t + 256];
    if (res) {
        v0 += res[base + t];
        v1 += res[base + t + 256];
    }

    red[t] = v0 + v1;
    __syncthreads();
    for (int off = 128; off > 0; off >>= 1) {
        if (t < off) red[t] += red[t + off];
        __syncthreads();
    }
    const float mean = red[0] * (1.f / HDIM);
    __syncthreads();

    const float d0 = v0 - mean, d1 = v1 - mean;
    red[t] = d0 * d0 + d1 * d1;
    __syncthreads();
    for (int off = 128; off > 0; off >>= 1) {
        if (t < off) red[t] += red[t + off];
        __syncthreads();
    }
    const float rs = rsqrtf(red[0] * (1.f / HDIM) + EPSV);

    out[base + t]       = d0 * rs * g[t] + bta[t];
    out[base + t + 256] = d1 * rs * g[t + 256] + bta[t + 256];
}

// ---------------------------------------------------------------------------
// Final batch-norm over B=8 samples of x[:,0,:]. out[b,h].
// ---------------------------------------------------------------------------
__global__ void bn_kernel(const float* __restrict__ x, const float* __restrict__ g,
                          const float* __restrict__ bb, float* __restrict__ out) {
    const int h = blockIdx.x * blockDim.x + threadIdx.x;
    if (h >= HDIM) return;
    float v[NB];
    float m = 0.f;
#pragma unroll
    for (int b = 0; b < NB; b++) {
        v[b] = x[(size_t)b * SQ * HDIM + h];
        m += v[b];
    }
    m *= (1.f / NB);
    float var = 0.f;
#pragma unroll
    for (int b = 0; b < NB; b++) {
        float d = v[b] - m;
        var += d * d;
    }
    var *= (1.f / NB);
    const float rs = rsqrtf(var + EPSV);
#pragma unroll
    for (int b = 0; b < NB; b++)
        out[b * HDIM + h] = (v[b] - m) * rs * g[h] + bb[h];
}

// ---------------------------------------------------------------------------
// Launch
// ---------------------------------------------------------------------------
extern "C" void kernel_launch(void* const* d_in, const int* in_sizes, int n_in,
                              void* d_out, int out_size) {
    (void)in_sizes; (void)n_in; (void)out_size;

    const float* nodes      = (const float*)d_in[0];
    const int*   dist       = (const int*)d_in[1];
    const float* dense_w    = (const float*)d_in[2];
    const float* dense_b    = (const float*)d_in[3];
    const float* dense_ln_g = (const float*)d_in[4];
    const float* dense_ln_b = (const float*)d_in[5];
    const float* qkv_w      = (const float*)d_in[6];
    const float* qkv_b      = (const float*)d_in[7];
    const float* out_w      = (const float*)d_in[8];
    const float* out_b      = (const float*)d_in[9];
    const float* ln1_g      = (const float*)d_in[10];
    const float* ln1_b      = (const float*)d_in[11];
    const float* ffn_w1     = (const float*)d_in[12];
    const float* ffn_b1     = (const float*)d_in[13];
    const float* ffn_w2     = (const float*)d_in[14];
    const float* ffn_b2     = (const float*)d_in[15];
    const float* ln2_g      = (const float*)d_in[16];
    const float* ln2_b      = (const float*)d_in[17];
    const float* bn_g       = (const float*)d_in[18];
    const float* bn_b       = (const float*)d_in[19];
    float* out = (float*)d_out;

    float *xin, *x, *qkv, *scores, *o, *ffn, *tmp;
    cudaGetSymbolAddress((void**)&xin,    g_xin);
    cudaGetSymbolAddress((void**)&x,      g_x);
    cudaGetSymbolAddress((void**)&qkv,    g_qkv);
    cudaGetSymbolAddress((void**)&scores, g_scores);
    cudaGetSymbolAddress((void**)&o,      g_o);
    cudaGetSymbolAddress((void**)&ffn,    g_ffn);
    cudaGetSymbolAddress((void**)&tmp,    g_tmp);

    const int M = NB * SQ;  // 8192 rows

    // input transpose + dense projection + LN
    transpose_nodes<<<(NB * SQ * ID + 255) / 256, 256>>>(nodes, xin);
    gemm_tn_tf32<<<dim3(HDIM / 128, M / 128), 256>>>(xin, ID, dense_w, ID, dense_b,
                                                     tmp, HDIM, ID, 0);
    ln_kernel<<<M, 256>>>(tmp, nullptr, dense_ln_g, dense_ln_b, x);

    for (int l = 0; l < NL; l++) {
        // QKV projection: [8192,512] @ [1536,512]^T
        gemm_tn_tf32<<<dim3(3 * HDIM / 128, M / 128), 256>>>(
            x, HDIM, qkv_w + (size_t)l * 3 * HDIM * HDIM, HDIM,
            qkv_b + l * 3 * HDIM, qkv, 3 * HDIM, HDIM, 0);

        // scores = QK^T * scale + mask-bias (fused), per (b,h)
        scores_gemm_tf32<<<dim3(SQ / 128, SQ / 128, NB * NHD), 256>>>(qkv, dist, scores);

        // softmax rows
        softmax_rows<<<NB * NHD * SQ, 256>>>(scores);

        // O = attn @ V
        av_gemm_tf32<<<dim3(SQ / 128, NB * NHD), 256>>>(scores, qkv, o);

        // output projection + residual LN
        gemm_tn_tf32<<<dim3(HDIM / 128, M / 128), 256>>>(
            o, HDIM, out_w + (size_t)l * HDIM * HDIM, HDIM,
            out_b + l * HDIM, tmp, HDIM, HDIM, 0);
        ln_kernel<<<M, 256>>>(tmp, x, ln1_g + l * HDIM, ln1_b + l * HDIM, x);

        // FFN
        gemm_tn_tf32<<<dim3(FFD / 128, M / 128), 256>>>(
            x, HDIM, ffn_w1 + (size_t)l * FFD * HDIM, HDIM,
            ffn_b1 + l * FFD, ffn, FFD, HDIM, 1);
        gemm_tn_tf32<<<dim3(HDIM / 128, M / 128), 256>>>(
            ffn, FFD, ffn_w2 + (size_t)l * HDIM * FFD, FFD,
            ffn_b2 + l * HDIM, tmp, HDIM, FFD, 0);
        ln_kernel<<<M, 256>>>(tmp, x, ln2_g + l * HDIM, ln2_b + l * HDIM, x);
    }

    // final batch-norm over batch dim of x[:, 0, :]
    bn_kernel<<<1, HDIM>>>(x, bn_g, bn_b, out);
}

// round 7
// speedup vs baseline: 2.8375x; 1.3122x over previous
#include <cuda_runtime.h>
#include <cstdint>
#include <math_constants.h>

// ---------------------------------------------------------------------------
// Problem constants
// ---------------------------------------------------------------------------
#define SQ   1024        // sequence length S
#define NB   8           // batch B
#define ID   256         // input dim I
#define HDIM 512         // hidden H
#define NL   4           // layers L
#define NHD  8           // num heads
#define HSZ  64          // head dim
#define FFD  1024        // ffn dim
#define EPSV 1e-5f
#define NEGV (-1e9f)

#define KT   16          // GEMM K tile
#define ASTR 20          // GEMM smem row stride (16 + 4 pad)

#define KSTR 68          // flash K/Q smem row stride (64 + 4) -> conflict-free
#define VSTR 72          // flash V smem row stride (64 + 8)  -> conflict-free

// ---------------------------------------------------------------------------
// Scratch (static device globals — no runtime allocation allowed)
// ---------------------------------------------------------------------------
__device__ float g_xin[NB * SQ * ID];
__device__ float g_x[NB * SQ * HDIM];
__device__ float g_qkv[NB * SQ * 3 * HDIM];
__device__ float g_o[NB * SQ * HDIM];
__device__ float g_ffn[NB * SQ * FFD];
__device__ float g_tmp[NB * SQ * HDIM];

// ---------------------------------------------------------------------------
// TF32 helpers
// ---------------------------------------------------------------------------
__device__ __forceinline__ float to_tf32(float x) {
    uint32_t u;
    asm("cvt.rna.tf32.f32 %0, %1;" : "=r"(u) : "f"(x));
    return __uint_as_float(u);
}

__device__ __forceinline__ void st_tf32(float* p, float4 v) {
    p[0] = to_tf32(v.x); p[1] = to_tf32(v.y);
    p[2] = to_tf32(v.z); p[3] = to_tf32(v.w);
}

__device__ __forceinline__ void mma_tf32(float* d, const uint32_t* a, const uint32_t* b) {
    asm volatile(
        "mma.sync.aligned.m16n8k8.row.col.f32.tf32.tf32.f32 "
        "{%0,%1,%2,%3}, {%4,%5,%6,%7}, {%8,%9}, {%0,%1,%2,%3};\n"
        : "+f"(d[0]), "+f"(d[1]), "+f"(d[2]), "+f"(d[3])
        : "r"(a[0]), "r"(a[1]), "r"(a[2]), "r"(a[3]), "r"(b[0]), "r"(b[1]));
}

// ---------------------------------------------------------------------------
// (S, B, I) -> (B, S, I)
// ---------------------------------------------------------------------------
__global__ void transpose_nodes(const float* __restrict__ nodes,
                                float* __restrict__ xin) {
    int idx = blockIdx.x * blockDim.x + threadIdx.x;
    if (idx >= NB * SQ * ID) return;
    int i  = idx % ID;
    int bs = idx / ID;
    int s  = bs % SQ;
    int b  = bs / SQ;
    xin[idx] = nodes[((size_t)s * NB + b) * ID + i];
}

// ---------------------------------------------------------------------------
// TF32 TN GEMM: C[m,n] = act( sum_k A[m,k] * W[n,k] + bias[n] )
// Block 128x128xKT, 8 warps (2M x 4N), warp tile 64x32, m16n8k8 MMA,
// double-buffered smem. Requires M%128==0, N%128==0, K%16==0.
// ---------------------------------------------------------------------------
__global__ void __launch_bounds__(256)
gemm_tn_tf32(const float* __restrict__ A, int lda,
             const float* __restrict__ W, int ldb,
             const float* __restrict__ bias,
             float* __restrict__ C, int ldc,
             int K, int relu) {
    __shared__ float As[2][128][ASTR];
    __shared__ float Bs[2][128][ASTR];

    const int tid = threadIdx.x;
    const int bm = blockIdx.y * 128, bn = blockIdx.x * 128;
    const int r = tid >> 2, c4 = (tid & 3) * 4;
    const int wid = tid >> 5, lane = tid & 31;
    const int wm = (wid & 1) * 64, wn = (wid >> 1) * 32;
    const int g = lane >> 2, tig = lane & 3;

    const float* Ap0 = A + (size_t)(bm + r) * lda + c4;
    const float* Ap1 = Ap0 + (size_t)64 * lda;
    const float* Wp0 = W + (size_t)(bn + r) * ldb + c4;
    const float* Wp1 = Wp0 + (size_t)64 * ldb;

    float acc[4][4][4];
#pragma unroll
    for (int mi = 0; mi < 4; mi++)
#pragma unroll
        for (int ni = 0; ni < 4; ni++)
#pragma unroll
            for (int c = 0; c < 4; c++) acc[mi][ni][c] = 0.f;

    float4 av0 = *(const float4*)Ap0;
    float4 av1 = *(const float4*)Ap1;
    float4 bv0 = *(const float4*)Wp0;
    float4 bv1 = *(const float4*)Wp1;
    st_tf32(&As[0][r][c4], av0);
    st_tf32(&As[0][r + 64][c4], av1);
    st_tf32(&Bs[0][r][c4], bv0);
    st_tf32(&Bs[0][r + 64][c4], bv1);
    __syncthreads();

    const int nt = K / KT;
    for (int t = 0; t < nt; t++) {
        const int buf = t & 1;
        if (t + 1 < nt) {
            const int ko = (t + 1) * KT;
            av0 = *(const float4*)(Ap0 + ko);
            av1 = *(const float4*)(Ap1 + ko);
            bv0 = *(const float4*)(Wp0 + ko);
            bv1 = *(const float4*)(Wp1 + ko);
        }
#pragma unroll
        for (int kk = 0; kk < KT; kk += 8) {
            uint32_t af[4][4], bf[4][2];
#pragma unroll
            for (int mi = 0; mi < 4; mi++) {
                const int row = wm + mi * 16 + g;
                af[mi][0] = __float_as_uint(As[buf][row][kk + tig]);
                af[mi][1] = __float_as_uint(As[buf][row + 8][kk + tig]);
                af[mi][2] = __float_as_uint(As[buf][row][kk + tig + 4]);
                af[mi][3] = __float_as_uint(As[buf][row + 8][kk + tig + 4]);
            }
#pragma unroll
            for (int ni = 0; ni < 4; ni++) {
                const int col = wn + ni * 8 + g;
                bf[ni][0] = __float_as_uint(Bs[buf][col][kk + tig]);
                bf[ni][1] = __float_as_uint(Bs[buf][col][kk + tig + 4]);
            }
#pragma unroll
            for (int mi = 0; mi < 4; mi++)
#pragma unroll
                for (int ni = 0; ni < 4; ni++)
                    mma_tf32(acc[mi][ni], af[mi], bf[ni]);
        }
        if (t + 1 < nt) {
            const int nb = buf ^ 1;
            st_tf32(&As[nb][r][c4], av0);
            st_tf32(&As[nb][r + 64][c4], av1);
            st_tf32(&Bs[nb][r][c4], bv0);
            st_tf32(&Bs[nb][r + 64][c4], bv1);
        }
        __syncthreads();
    }

#pragma unroll
    for (int mi = 0; mi < 4; mi++) {
        const int row0 = bm + wm + mi * 16 + g;
        const int row1 = row0 + 8;
#pragma unroll
        for (int ni = 0; ni < 4; ni++) {
            const int col = bn + wn + ni * 8 + 2 * tig;
            const float b0 = bias[col], b1 = bias[col + 1];
            float v0 = acc[mi][ni][0] + b0;
            float v1 = acc[mi][ni][1] + b1;
            float v2 = acc[mi][ni][2] + b0;
            float v3 = acc[mi][ni][3] + b1;
            if (relu) {
                v0 = fmaxf(v0, 0.f); v1 = fmaxf(v1, 0.f);
                v2 = fmaxf(v2, 0.f); v3 = fmaxf(v3, 0.f);
            }
            *(float2*)(C + (size_t)row0 * ldc + col) = make_float2(v0, v1);
            *(float2*)(C + (size_t)row1 * ldc + col) = make_float2(v2, v3);
        }
    }
}

// ---------------------------------------------------------------------------
// Fused flash attention: per (b, h, 128-row q tile), online softmax,
// scores never hit memory. 256 threads = 8 warps, each warp owns 16 q rows.
// Q (scaled, tf32) lives in registers as A-fragments; K/V staged per 64-kv
// tile in smem; P converted C->A layout with register shuffles.
// ---------------------------------------------------------------------------
__global__ void __launch_bounds__(256)
flash_attn(const float* __restrict__ qkv, const int* __restrict__ dist,
           float* __restrict__ o) {
    __shared__ float sm[64 * KSTR + 64 * VSTR];   // 8960 floats; Q overlays it
    float* Qs = sm;                               // [128][KSTR] (prologue only)
    float* Ks = sm;                               // [64][KSTR]
    float* Vs = sm + 64 * KSTR;                   // [64][VSTR]

    const int bz = blockIdx.y;
    const int b = bz >> 3, h = bz & 7;
    const int q0 = blockIdx.x * 128;
    const int tid = threadIdx.x;
    const int w = tid >> 5, lane = tid & 31;
    const int g = lane >> 2, tig = lane & 3;
    const int rq = w * 16 + g;                    // local q row (first of pair)
    const bool row_head = (h < 6), shorth = (h < 4);

    // ---- stage Q tile (x 1/8 scale, tf32) and pull A-fragments ----
    {
        const int r = tid >> 2, c16 = (tid & 3) * 16;
        const float* src0 = qkv + ((size_t)(b * SQ + q0 + r) * (3 * HDIM)) + h * HSZ + c16;
#pragma unroll
        for (int it = 0; it < 2; it++) {
            const float* src = src0 + (size_t)it * 64 * (3 * HDIM);
            float* dst = Qs + (r + it * 64) * KSTR + c16;
#pragma unroll
            for (int i = 0; i < 4; i++) {
                float4 v = *(const float4*)(src + i * 4);
                dst[i * 4 + 0] = to_tf32(v.x * 0.125f);
                dst[i * 4 + 1] = to_tf32(v.y * 0.125f);
                dst[i * 4 + 2] = to_tf32(v.z * 0.125f);
                dst[i * 4 + 3] = to_tf32(v.w * 0.125f);
            }
        }
    }
    __syncthreads();

    uint32_t qf[8][4];
#pragma unroll
    for (int kc = 0; kc < 8; kc++) {
        qf[kc][0] = __float_as_uint(Qs[rq * KSTR + kc * 8 + tig]);
        qf[kc][1] = __float_as_uint(Qs[(rq + 8) * KSTR + kc * 8 + tig]);
        qf[kc][2] = __float_as_uint(Qs[rq * KSTR + kc * 8 + tig + 4]);
        qf[kc][3] = __float_as_uint(Qs[(rq + 8) * KSTR + kc * 8 + tig + 4]);
    }
    __syncthreads();

    float acc_o[8][4];
#pragma unroll
    for (int j = 0; j < 8; j++)
#pragma unroll
        for (int c = 0; c < 4; c++) acc_o[j][c] = 0.f;

    float m0 = -CUDART_INF_F, m1 = -CUDART_INF_F, l0 = 0.f, l1 = 0.f;
    const int gr0 = q0 + rq, gr1 = gr0 + 8;       // global q rows
    const int* dr0 = dist + (size_t)b * SQ * SQ + (row_head ? (size_t)gr0 * SQ : 0);
    const int* dr1 = row_head ? dr0 + 8 * SQ : dr0;

    for (int t = 0; t < SQ / 64; t++) {
        const int kv0 = t * 64;
        // ---- stage K, V (tf32) ----
        {
            const int r = tid >> 2, c16 = (tid & 3) * 16;
            const float* ksrc = qkv + ((size_t)(b * SQ + kv0 + r) * (3 * HDIM)) +
                                HDIM + h * HSZ + c16;
            const float* vsrc = ksrc + HDIM;
            float* kd = Ks + r * KSTR + c16;
            float* vd = Vs + r * VSTR + c16;
#pragma unroll
            for (int i = 0; i < 4; i++) {
                st_tf32(kd + i * 4, *(const float4*)(ksrc + i * 4));
                st_tf32(vd + i * 4, *(const float4*)(vsrc + i * 4));
            }
        }
        __syncthreads();

        // ---- S = Q @ K^T (already scaled) ----
        float acc_s[8][4];
#pragma unroll
        for (int j = 0; j < 8; j++)
#pragma unroll
            for (int c = 0; c < 4; c++) acc_s[j][c] = 0.f;

#pragma unroll
        for (int kc = 0; kc < 8; kc++) {
#pragma unroll
            for (int j = 0; j < 8; j++) {
                uint32_t bf[2];
                bf[0] = __float_as_uint(Ks[(j * 8 + g) * KSTR + kc * 8 + tig]);
                bf[1] = __float_as_uint(Ks[(j * 8 + g) * KSTR + kc * 8 + tig + 4]);
                mma_tf32(acc_s[j], qf[kc], bf);
            }
        }

        // ---- mask bias + tile max ----
        float tm0 = -CUDART_INF_F, tm1 = -CUDART_INF_F;
#pragma unroll
        for (int j = 0; j < 8; j++) {
            const int c0 = kv0 + j * 8 + 2 * tig, c1 = c0 + 1;
            const int d00 = dr0[c0], d01 = dr0[c1];
            const int d10 = dr1[c0], d11 = dr1[c1];
            const bool a00 = (gr0 == c0) || (shorth ? (d00 == 1) : (d00 >= 1));
            const bool a01 = (gr0 == c1) || (shorth ? (d01 == 1) : (d01 >= 1));
            const bool a10 = (gr1 == c0) || (shorth ? (d10 == 1) : (d10 >= 1));
            const bool a11 = (gr1 == c1) || (shorth ? (d11 == 1) : (d11 >= 1));
            acc_s[j][0] += a00 ? 0.f : NEGV;
            acc_s[j][1] += a01 ? 0.f : NEGV;
            acc_s[j][2] += a10 ? 0.f : NEGV;
            acc_s[j][3] += a11 ? 0.f : NEGV;
            tm0 = fmaxf(tm0, fmaxf(acc_s[j][0], acc_s[j][1]));
            tm1 = fmaxf(tm1, fmaxf(acc_s[j][2], acc_s[j][3]));
        }
        tm0 = fmaxf(tm0, __shfl_xor_sync(0xffffffffu, tm0, 1));
        tm0 = fmaxf(tm0, __shfl_xor_sync(0xffffffffu, tm0, 2));
        tm1 = fmaxf(tm1, __shfl_xor_sync(0xffffffffu, tm1, 1));
        tm1 = fmaxf(tm1, __shfl_xor_sync(0xffffffffu, tm1, 2));

        // ---- online softmax update ----
        const float mn0 = fmaxf(m0, tm0), mn1 = fmaxf(m1, tm1);
        const float al0 = __expf(m0 - mn0), al1 = __expf(m1 - mn1);
        float rs0 = 0.f, rs1 = 0.f;
#pragma unroll
        for (int j = 0; j < 8; j++) {
            acc_s[j][0] = __expf(acc_s[j][0] - mn0);
            acc_s[j][1] = __expf(acc_s[j][1] - mn0);
            acc_s[j][2] = __expf(acc_s[j][2] - mn1);
            acc_s[j][3] = __expf(acc_s[j][3] - mn1);
            rs0 += acc_s[j][0] + acc_s[j][1];
            rs1 += acc_s[j][2] + acc_s[j][3];
        }
        rs0 += __shfl_xor_sync(0xffffffffu, rs0, 1);
        rs0 += __shfl_xor_sync(0xffffffffu, rs0, 2);
        rs1 += __shfl_xor_sync(0xffffffffu, rs1, 1);
        rs1 += __shfl_xor_sync(0xffffffffu, rs1, 2);
        l0 = l0 * al0 + rs0;
        l1 = l1 * al1 + rs1;
        m0 = mn0; m1 = mn1;
#pragma unroll
        for (int j = 0; j < 8; j++) {
            acc_o[j][0] *= al0; acc_o[j][1] *= al0;
            acc_o[j][2] *= al1; acc_o[j][3] *= al1;
        }

        // ---- P: C-layout (rows {g,g+8}, cols {2tig,2tig+1}) ->
        //          A-layout (rows {g,g+8}, cols {tig,tig+4}) via quad shuffles ----
        const int sa = (lane & 28) | (tig >> 1);
        const int sb = sa + 2;
        const bool odd = tig & 1;
#pragma unroll
        for (int j = 0; j < 8; j++) {
            float v0a = __shfl_sync(0xffffffffu, acc_s[j][0], sa);
            float v1a = __shfl_sync(0xffffffffu, acc_s[j][1], sa);
            float v2a = __shfl_sync(0xffffffffu, acc_s[j][2], sa);
            float v3a = __shfl_sync(0xffffffffu, acc_s[j][3], sa);
            float v0b = __shfl_sync(0xffffffffu, acc_s[j][0], sb);
            float v1b = __shfl_sync(0xffffffffu, acc_s[j][1], sb);
            float v2b = __shfl_sync(0xffffffffu, acc_s[j][2], sb);
            float v3b = __shfl_sync(0xffffffffu, acc_s[j][3], sb);
            acc_s[j][0] = to_tf32(odd ? v1a : v0a);
            acc_s[j][1] = to_tf32(odd ? v3a : v2a);
            acc_s[j][2] = to_tf32(odd ? v1b : v0b);
            acc_s[j][3] = to_tf32(odd ? v3b : v2b);
        }

        // ---- O += P @ V ----
#pragma unroll
        for (int kc = 0; kc < 8; kc++) {
            uint32_t pa[4];
            pa[0] = __float_as_uint(acc_s[kc][0]);
            pa[1] = __float_as_uint(acc_s[kc][1]);
            pa[2] = __float_as_uint(acc_s[kc][2]);
            pa[3] = __float_as_uint(acc_s[kc][3]);
#pragma unroll
            for (int jd = 0; jd < 8; jd++) {
                uint32_t bf[2];
                bf[0] = __float_as_uint(Vs[(kc * 8 + tig) * VSTR + jd * 8 + g]);
                bf[1] = __float_as_uint(Vs[(kc * 8 + tig + 4) * VSTR + jd * 8 + g]);
                mma_tf32(acc_o[jd], pa, bf);
            }
        }
        __syncthreads();
    }

    // ---- epilogue: O /= l ----
    const float inv0 = 1.f / l0, inv1 = 1.f / l1;
    float* ob = o + ((size_t)(b * SQ + gr0) * HDIM) + h * HSZ;
#pragma unroll
    for (int jd = 0; jd < 8; jd++) {
        const int c = jd * 8 + 2 * tig;
        *(float2*)(ob + c) = make_float2(acc_o[jd][0] * inv0, acc_o[jd][1] * inv0);
        *(float2*)(ob + (size_t)8 * HDIM + c) =
            make_float2(acc_o[jd][2] * inv1, acc_o[jd][3] * inv1);
    }
}

// ---------------------------------------------------------------------------
// LayerNorm over H=512, optional residual add. One block (256 thr) per row.
// ---------------------------------------------------------------------------
__global__ void __launch_bounds__(256)
ln_kernel(const float* __restrict__ y, const float* __restrict__ res,
          const float* __restrict__ g, const float* __restrict__ bta,
          float* __restrict__ out) {
    __shared__ float red[256];
    const int t = threadIdx.x;
    const size_t base = (size_t)blockIdx.x * HDIM;

    float v0 = y[base + t];
    float v1 = y[base + t + 256];
    if (res) {
        v0 += res[base + t];
        v1 += res[base + t + 256];
    }

    red[t] = v0 + v1;
    __syncthreads();
    for (int off = 128; off > 0; off >>= 1) {
        if (t < off) red[t] += red[t + off];
        __syncthreads();
    }
    const float mean = red[0] * (1.f / HDIM);
    __syncthreads();

    const float d0 = v0 - mean, d1 = v1 - mean;
    red[t] = d0 * d0 + d1 * d1;
    __syncthreads();
    for (int off = 128; off > 0; off >>= 1) {
        if (t < off) red[t] += red[t + off];
        __syncthreads();
    }
    const float rs = rsqrtf(red[0] * (1.f / HDIM) + EPSV);

    out[base + t]       = d0 * rs * g[t] + bta[t];
    out[base + t + 256] = d1 * rs * g[t + 256] + bta[t + 256];
}

// ---------------------------------------------------------------------------
// Final batch-norm over B=8 samples of x[:,0,:]. out[b,h].
// ---------------------------------------------------------------------------
__global__ void bn_kernel(const float* __restrict__ x, const float* __restrict__ g,
                          const float* __restrict__ bb, float* __restrict__ out) {
    const int h = blockIdx.x * blockDim.x + threadIdx.x;
    if (h >= HDIM) return;
    float v[NB];
    float m = 0.f;
#pragma unroll
    for (int b = 0; b < NB; b++) {
        v[b] = x[(size_t)b * SQ * HDIM + h];
        m += v[b];
    }
    m *= (1.f / NB);
    float var = 0.f;
#pragma unroll
    for (int b = 0; b < NB; b++) {
        float d = v[b] - m;
        var += d * d;
    }
    var *= (1.f / NB);
    const float rs = rsqrtf(var + EPSV);
#pragma unroll
    for (int b = 0; b < NB; b++)
        out[b * HDIM + h] = (v[b] - m) * rs * g[h] + bb[h];
}

// ---------------------------------------------------------------------------
// Launch
// ---------------------------------------------------------------------------
extern "C" void kernel_launch(void* const* d_in, const int* in_sizes, int n_in,
                              void* d_out, int out_size) {
    (void)in_sizes; (void)n_in; (void)out_size;

    const float* nodes      = (const float*)d_in[0];
    const int*   dist       = (const int*)d_in[1];
    const float* dense_w    = (const float*)d_in[2];
    const float* dense_b    = (const float*)d_in[3];
    const float* dense_ln_g = (const float*)d_in[4];
    const float* dense_ln_b = (const float*)d_in[5];
    const float* qkv_w      = (const float*)d_in[6];
    const float* qkv_b      = (const float*)d_in[7];
    const float* out_w      = (const float*)d_in[8];
    const float* out_b      = (const float*)d_in[9];
    const float* ln1_g      = (const float*)d_in[10];
    const float* ln1_b      = (const float*)d_in[11];
    const float* ffn_w1     = (const float*)d_in[12];
    const float* ffn_b1     = (const float*)d_in[13];
    const float* ffn_w2     = (const float*)d_in[14];
    const float* ffn_b2     = (const float*)d_in[15];
    const float* ln2_g      = (const float*)d_in[16];
    const float* ln2_b      = (const float*)d_in[17];
    const float* bn_g       = (const float*)d_in[18];
    const float* bn_b       = (const float*)d_in[19];
    float* out = (float*)d_out;

    float *xin, *x, *qkv, *o, *ffn, *tmp;
    cudaGetSymbolAddress((void**)&xin, g_xin);
    cudaGetSymbolAddress((void**)&x,   g_x);
    cudaGetSymbolAddress((void**)&qkv, g_qkv);
    cudaGetSymbolAddress((void**)&o,   g_o);
    cudaGetSymbolAddress((void**)&ffn, g_ffn);
    cudaGetSymbolAddress((void**)&tmp, g_tmp);

    const int M = NB * SQ;  // 8192 rows

    // input transpose + dense projection + LN
    transpose_nodes<<<(NB * SQ * ID + 255) / 256, 256>>>(nodes, xin);
    gemm_tn_tf32<<<dim3(HDIM / 128, M / 128), 256>>>(xin, ID, dense_w, ID, dense_b,
                                                     tmp, HDIM, ID, 0);
    ln_kernel<<<M, 256>>>(tmp, nullptr, dense_ln_g, dense_ln_b, x);

    for (int l = 0; l < NL; l++) {
        // QKV projection: [8192,512] @ [1536,512]^T
        gemm_tn_tf32<<<dim3(3 * HDIM / 128, M / 128), 256>>>(
            x, HDIM, qkv_w + (size_t)l * 3 * HDIM * HDIM, HDIM,
            qkv_b + l * 3 * HDIM, qkv, 3 * HDIM, HDIM, 0);

        // fused attention (scores + mask + softmax + AV)
        flash_attn<<<dim3(SQ / 128, NB * NHD), 256>>>(qkv, dist, o);

        // output projection + residual LN
        gemm_tn_tf32<<<dim3(HDIM / 128, M / 128), 256>>>(
            o, HDIM, out_w + (size_t)l * HDIM * HDIM, HDIM,
            out_b + l * HDIM, tmp, HDIM, HDIM, 0);
        ln_kernel<<<M, 256>>>(tmp, x, ln1_g + l * HDIM, ln1_b + l * HDIM, x);

        // FFN
        gemm_tn_tf32<<<dim3(FFD / 128, M / 128), 256>>>(
            x, HDIM, ffn_w1 + (size_t)l * FFD * HDIM, HDIM,
            ffn_b1 + l * FFD, ffn, FFD, HDIM, 1);
        gemm_tn_tf32<<<dim3(HDIM / 128, M / 128), 256>>>(
            ffn, FFD, ffn_w2 + (size_t)l * HDIM * FFD, FFD,
            ffn_b2 + l * HDIM, tmp, HDIM, FFD, 0);
        ln_kernel<<<M, 256>>>(tmp, x, ln2_g + l * HDIM, ln2_b + l * HDIM, x);
    }

    // final batch-norm over batch dim of x[:, 0, :]
    bn_kernel<<<1, HDIM>>>(x, bn_g, bn_b, out);
}

// round 12
// speedup vs baseline: 3.1292x; 1.1028x over previous
#include <cuda_runtime.h>
#include <cstdint>
#include <math_constants.h>

// ---------------------------------------------------------------------------
// Problem constants
// ---------------------------------------------------------------------------
#define SQ   1024        // sequence length S
#define NB   8           // batch B
#define ID   256         // input dim I
#define HDIM 512         // hidden H
#define NL   4           // layers L
#define NHD  8           // num heads
#define HSZ  64          // head dim
#define FFD  1024        // ffn dim
#define EPSV 1e-5f
#define NEGV (-1e9f)

#define KT   16          // GEMM K tile
#define ASTR 20          // GEMM smem row stride (16+4): (20/4)=5 odd -> LDSM ok
#define KSTR 68          // flash K/Q smem row stride (64+4): 17 odd -> LDSM ok
#define VSTR 68          // flash V^T smem row stride

// ---------------------------------------------------------------------------
// Scratch (static device globals — no runtime allocation allowed)
// ---------------------------------------------------------------------------
__device__ float g_xin[NB * SQ * ID];
__device__ float g_x[NB * SQ * HDIM];
__device__ float g_qkv[NB * SQ * 3 * HDIM];
__device__ float g_o[NB * SQ * HDIM];
__device__ float g_ffn[NB * SQ * FFD];
__device__ float g_tmp[NB * SQ * HDIM];

// ---------------------------------------------------------------------------
// TF32 / MMA / LDSM helpers
// ---------------------------------------------------------------------------
__device__ __forceinline__ float to_tf32(float x) {
    uint32_t u;
    asm("cvt.rna.tf32.f32 %0, %1;" : "=r"(u) : "f"(x));
    return __uint_as_float(u);
}

__device__ __forceinline__ void st_tf32(float* p, float4 v) {
    p[0] = to_tf32(v.x); p[1] = to_tf32(v.y);
    p[2] = to_tf32(v.z); p[3] = to_tf32(v.w);
}

__device__ __forceinline__ void mma_tf32(float* d, const uint32_t* a, const uint32_t* b) {
    asm volatile(
        "mma.sync.aligned.m16n8k8.row.col.f32.tf32.tf32.f32 "
        "{%0,%1,%2,%3}, {%4,%5,%6,%7}, {%8,%9}, {%0,%1,%2,%3};\n"
        : "+f"(d[0]), "+f"(d[1]), "+f"(d[2]), "+f"(d[3])
        : "r"(a[0]), "r"(a[1]), "r"(a[2]), "r"(a[3]), "r"(b[0]), "r"(b[1]));
}

__device__ __forceinline__ uint32_t smem_u32(const void* p) {
    return (uint32_t)__cvta_generic_to_shared(p);
}

// x4 ldmatrix: four 8x8 b16 tiles == four (8 row x 4 tf32-col) tiles.
// Lane l of tile q receives 32-bit element (row l/4, col l%4).
__device__ __forceinline__ void ldsm4(uint32_t* r, uint32_t a) {
    asm volatile(
        "ldmatrix.sync.aligned.m8n8.x4.shared.b16 {%0,%1,%2,%3}, [%4];"
        : "=r"(r[0]), "=r"(r[1]), "=r"(r[2]), "=r"(r[3]) : "r"(a));
}

// ---------------------------------------------------------------------------
// (S, B, I) -> (B, S, I)
// ---------------------------------------------------------------------------
__global__ void transpose_nodes(const float* __restrict__ nodes,
                                float* __restrict__ xin) {
    int idx = blockIdx.x * blockDim.x + threadIdx.x;
    if (idx >= NB * SQ * ID) return;
    int i  = idx % ID;
    int bs = idx / ID;
    int s  = bs % SQ;
    int b  = bs / SQ;
    xin[idx] = nodes[((size_t)s * NB + b) * ID + i];
}

// ---------------------------------------------------------------------------
// TF32 TN GEMM: C[m,n] = act( sum_k A[m,k] * W[n,k] + bias[n] )
// Block 128x128xKT, 8 warps (2M x 4N), warp tile 64x32, m16n8k8 MMA,
// double-buffered smem, ldmatrix fragment loads.
// ---------------------------------------------------------------------------
__global__ void __launch_bounds__(256)
gemm_tn_tf32(const float* __restrict__ A, int lda,
             const float* __restrict__ W, int ldb,
             const float* __restrict__ bias,
             float* __restrict__ C, int ldc,
             int K, int relu) {
    __shared__ float As[2][128][ASTR];
    __shared__ float Bs[2][128][ASTR];
    const uint32_t BUFO = 128 * ASTR * 4;   // bytes per buffer

    const int tid = threadIdx.x;
    const int bm = blockIdx.y * 128, bn = blockIdx.x * 128;
    const int r = tid >> 2, c4 = (tid & 3) * 4;
    const int wid = tid >> 5, lane = tid & 31;
    const int wm = (wid & 1) * 64, wn = (wid >> 1) * 32;
    const int qt = lane >> 3, rr = lane & 7;

    // ldmatrix addresses (buffer 0, kk 0)
    uint32_t a_addr[4], b_addr[2];
#pragma unroll
    for (int mi = 0; mi < 4; mi++)
        a_addr[mi] = smem_u32(&As[0][wm + mi * 16 + (qt & 1) * 8 + rr][(qt >> 1) * 4]);
#pragma unroll
    for (int p = 0; p < 2; p++)
        b_addr[p] = smem_u32(&Bs[0][wn + p * 16 + (qt >> 1) * 8 + rr][(qt & 1) * 4]);

    const float* Ap0 = A + (size_t)(bm + r) * lda + c4;
    const float* Ap1 = Ap0 + (size_t)64 * lda;
    const float* Wp0 = W + (size_t)(bn + r) * ldb + c4;
    const float* Wp1 = Wp0 + (size_t)64 * ldb;

    float acc[4][4][4];
#pragma unroll
    for (int mi = 0; mi < 4; mi++)
#pragma unroll
        for (int ni = 0; ni < 4; ni++)
#pragma unroll
            for (int c = 0; c < 4; c++) acc[mi][ni][c] = 0.f;

    float4 av0 = *(const float4*)Ap0;
    float4 av1 = *(const float4*)Ap1;
    float4 bv0 = *(const float4*)Wp0;
    float4 bv1 = *(const float4*)Wp1;
    st_tf32(&As[0][r][c4], av0);
    st_tf32(&As[0][r + 64][c4], av1);
    st_tf32(&Bs[0][r][c4], bv0);
    st_tf32(&Bs[0][r + 64][c4], bv1);
    __syncthreads();

    const int nt = K / KT;
    for (int t = 0; t < nt; t++) {
        const uint32_t off = (uint32_t)(t & 1) * BUFO;
        if (t + 1 < nt) {
            const int ko = (t + 1) * KT;
            av0 = *(const float4*)(Ap0 + ko);
            av1 = *(const float4*)(Ap1 + ko);
            bv0 = *(const float4*)(Wp0 + ko);
            bv1 = *(const float4*)(Wp1 + ko);
        }
#pragma unroll
        for (int kk = 0; kk < KT; kk += 8) {
            uint32_t af[4][4], bfr[2][4];
#pragma unroll
            for (int mi = 0; mi < 4; mi++)
                ldsm4(af[mi], a_addr[mi] + off + kk * 4);
#pragma unroll
            for (int p = 0; p < 2; p++)
                ldsm4(bfr[p], b_addr[p] + off + kk * 4);
#pragma unroll
            for (int mi = 0; mi < 4; mi++)
#pragma unroll
                for (int ni = 0; ni < 4; ni++)
                    mma_tf32(acc[mi][ni], af[mi], &bfr[ni >> 1][(ni & 1) * 2]);
        }
        if (t + 1 < nt) {
            const int nb = (t + 1) & 1;
            st_tf32(&As[nb][r][c4], av0);
            st_tf32(&As[nb][r + 64][c4], av1);
            st_tf32(&Bs[nb][r][c4], bv0);
            st_tf32(&Bs[nb][r + 64][c4], bv1);
        }
        __syncthreads();
    }

    const int g = lane >> 2, tig = lane & 3;
#pragma unroll
    for (int mi = 0; mi < 4; mi++) {
        const int row0 = bm + wm + mi * 16 + g;
        const int row1 = row0 + 8;
#pragma unroll
        for (int ni = 0; ni < 4; ni++) {
            const int col = bn + wn + ni * 8 + 2 * tig;
            const float b0 = bias[col], b1 = bias[col + 1];
            float v0 = acc[mi][ni][0] + b0;
            float v1 = acc[mi][ni][1] + b1;
            float v2 = acc[mi][ni][2] + b0;
            float v3 = acc[mi][ni][3] + b1;
            if (relu) {
                v0 = fmaxf(v0, 0.f); v1 = fmaxf(v1, 0.f);
                v2 = fmaxf(v2, 0.f); v3 = fmaxf(v3, 0.f);
            }
            *(float2*)(C + (size_t)row0 * ldc + col) = make_float2(v0, v1);
            *(float2*)(C + (size_t)row1 * ldc + col) = make_float2(v2, v3);
        }
    }
}

// ---------------------------------------------------------------------------
// Fused flash attention with ldmatrix fragment loads.
// Per (b, h, 128-row q tile); 8 warps x 16 q rows; online softmax.
// K staged [kv][d] (row-major), V staged TRANSPOSED [d][kv] so both feed
// B-fragments via ldmatrix.
// ---------------------------------------------------------------------------
__global__ void __launch_bounds__(256)
flash_attn(const float* __restrict__ qkv, const int* __restrict__ dist,
           float* __restrict__ o) {
    __shared__ float sm[64 * KSTR + 64 * VSTR];   // 8704 floats; Q overlays it
    float* Qs = sm;                               // [128][KSTR] (prologue only)
    float* Ks = sm;                               // [64][KSTR]  rows = kv
    float* Vt = sm + 64 * KSTR;                   // [64][VSTR]  rows = d (V^T)

    const int bz = blockIdx.y;
    const int b = bz >> 3, h = bz & 7;
    const int q0 = blockIdx.x * 128;
    const int tid = threadIdx.x;
    const int w = tid >> 5, lane = tid & 31;
    const int g = lane >> 2, tig = lane & 3;
    const int qt = lane >> 3, rr = lane & 7;
    const int rq = w * 16 + g;                    // local q row (first of pair)
    const bool row_head = (h < 6), shorth = (h < 4);

    // ---- stage Q tile (x 1/8 scale, tf32) and pull A-fragments ----
    {
        const int r = tid >> 2, c16 = (tid & 3) * 16;
        const float* src0 = qkv + ((size_t)(b * SQ + q0 + r) * (3 * HDIM)) + h * HSZ + c16;
#pragma unroll
        for (int it = 0; it < 2; it++) {
            const float* src = src0 + (size_t)it * 64 * (3 * HDIM);
            float* dst = Qs + (r + it * 64) * KSTR + c16;
#pragma unroll
            for (int i = 0; i < 4; i++) {
                float4 v = *(const float4*)(src + i * 4);
                dst[i * 4 + 0] = to_tf32(v.x * 0.125f);
                dst[i * 4 + 1] = to_tf32(v.y * 0.125f);
                dst[i * 4 + 2] = to_tf32(v.z * 0.125f);
                dst[i * 4 + 3] = to_tf32(v.w * 0.125f);
            }
        }
    }
    __syncthreads();

    uint32_t qf[8][4];
    {
        const uint32_t qa = smem_u32(Qs + (rq - g + (qt & 1) * 8 + rr) * KSTR + (qt >> 1) * 4);
#pragma unroll
        for (int kc = 0; kc < 8; kc++) ldsm4(qf[kc], qa + kc * 32);
    }
    __syncthreads();

    // ldmatrix addresses for K and V^T fragments (fixed for all tiles)
    uint32_t kf_addr[4], vf_addr[4];
#pragma unroll
    for (int p = 0; p < 4; p++) {
        kf_addr[p] = smem_u32(Ks + (p * 16 + (qt >> 1) * 8 + rr) * KSTR + (qt & 1) * 4);
        vf_addr[p] = smem_u32(Vt + (p * 16 + (qt >> 1) * 8 + rr) * VSTR + (qt & 1) * 4);
    }

    float acc_o[8][4];
#pragma unroll
    for (int j = 0; j < 8; j++)
#pragma unroll
        for (int c = 0; c < 4; c++) acc_o[j][c] = 0.f;

    float m0 = -CUDART_INF_F, m1 = -CUDART_INF_F, l0 = 0.f, l1 = 0.f;
    const int gr0 = q0 + rq, gr1 = gr0 + 8;       // global q rows
    const int* dr0 = dist + (size_t)b * SQ * SQ + (row_head ? (size_t)gr0 * SQ : 0);
    const int* dr1 = row_head ? dr0 + 8 * SQ : dr0;

    for (int t = 0; t < SQ / 64; t++) {
        const int kv0 = t * 64;
        // ---- stage K [kv][d] ----
        {
            const int r = tid >> 2, c16 = (tid & 3) * 16;
            const float* ksrc = qkv + ((size_t)(b * SQ + kv0 + r) * (3 * HDIM)) +
                                HDIM + h * HSZ + c16;
            float* kd = Ks + r * KSTR + c16;
#pragma unroll
            for (int i = 0; i < 4; i++)
                st_tf32(kd + i * 4, *(const float4*)(ksrc + i * 4));
        }
        // ---- stage V transposed: Vt[d][kv] (conflict-free scalar STS) ----
        {
            const int rv = tid & 63, cv = (tid >> 6) * 16;
            const float* vsrc = qkv + ((size_t)(b * SQ + kv0 + rv) * (3 * HDIM)) +
                                2 * HDIM + h * HSZ + cv;
#pragma unroll
            for (int i = 0; i < 4; i++) {
                float4 v = *(const float4*)(vsrc + i * 4);
                Vt[(cv + i * 4 + 0) * VSTR + rv] = to_tf32(v.x);
                Vt[(cv + i * 4 + 1) * VSTR + rv] = to_tf32(v.y);
                Vt[(cv + i * 4 + 2) * VSTR + rv] = to_tf32(v.z);
                Vt[(cv + i * 4 + 3) * VSTR + rv] = to_tf32(v.w);
            }
        }
        __syncthreads();

        // ---- S = Q @ K^T (already scaled) ----
        float acc_s[8][4];
#pragma unroll
        for (int j = 0; j < 8; j++)
#pragma unroll
            for (int c = 0; c < 4; c++) acc_s[j][c] = 0.f;

#pragma unroll
        for (int kc = 0; kc < 8; kc++) {
            uint32_t kb[4][4];
#pragma unroll
            for (int p = 0; p < 4; p++) ldsm4(kb[p], kf_addr[p] + kc * 32);
#pragma unroll
            for (int j = 0; j < 8; j++)
                mma_tf32(acc_s[j], qf[kc], &kb[j >> 1][(j & 1) * 2]);
        }

        // ---- mask bias + tile max ----
        float tm0 = -CUDART_INF_F, tm1 = -CUDART_INF_F;
#pragma unroll
        for (int j = 0; j < 8; j++) {
            const int c0 = kv0 + j * 8 + 2 * tig, c1 = c0 + 1;
            const int d00 = dr0[c0], d01 = dr0[c1];
            const int d10 = dr1[c0], d11 = dr1[c1];
            const bool a00 = (gr0 == c0) || (shorth ? (d00 == 1) : (d00 >= 1));
            const bool a01 = (gr0 == c1) || (shorth ? (d01 == 1) : (d01 >= 1));
            const bool a10 = (gr1 == c0) || (shorth ? (d10 == 1) : (d10 >= 1));
            const bool a11 = (gr1 == c1) || (shorth ? (d11 == 1) : (d11 >= 1));
            acc_s[j][0] += a00 ? 0.f : NEGV;
            acc_s[j][1] += a01 ? 0.f : NEGV;
            acc_s[j][2] += a10 ? 0.f : NEGV;
            acc_s[j][3] += a11 ? 0.f : NEGV;
            tm0 = fmaxf(tm0, fmaxf(acc_s[j][0], acc_s[j][1]));
            tm1 = fmaxf(tm1, fmaxf(acc_s[j][2], acc_s[j][3]));
        }
        tm0 = fmaxf(tm0, __shfl_xor_sync(0xffffffffu, tm0, 1));
        tm0 = fmaxf(tm0, __shfl_xor_sync(0xffffffffu, tm0, 2));
        tm1 = fmaxf(tm1, __shfl_xor_sync(0xffffffffu, tm1, 1));
        tm1 = fmaxf(tm1, __shfl_xor_sync(0xffffffffu, tm1, 2));

        // ---- online softmax update ----
        const float mn0 = fmaxf(m0, tm0), mn1 = fmaxf(m1, tm1);
        const float al0 = __expf(m0 - mn0), al1 = __expf(m1 - mn1);
        float rs0 = 0.f, rs1 = 0.f;
#pragma unroll
        for (int j = 0; j < 8; j++) {
            acc_s[j][0] = __expf(acc_s[j][0] - mn0);
            acc_s[j][1] = __expf(acc_s[j][1] - mn0);
            acc_s[j][2] = __expf(acc_s[j][2] - mn1);
            acc_s[j][3] = __expf(acc_s[j][3] - mn1);
            rs0 += acc_s[j][0] + acc_s[j][1];
            rs1 += acc_s[j][2] + acc_s[j][3];
        }
        rs0 += __shfl_xor_sync(0xffffffffu, rs0, 1);
        rs0 += __shfl_xor_sync(0xffffffffu, rs0, 2);
        rs1 += __shfl_xor_sync(0xffffffffu, rs1, 1);
        rs1 += __shfl_xor_sync(0xffffffffu, rs1, 2);
        l0 = l0 * al0 + rs0;
        l1 = l1 * al1 + rs1;
        m0 = mn0; m1 = mn1;
#pragma unroll
        for (int j = 0; j < 8; j++) {
            acc_o[j][0] *= al0; acc_o[j][1] *= al0;
            acc_o[j][2] *= al1; acc_o[j][3] *= al1;
        }

        // ---- P: C-layout -> A-layout via quad shuffles ----
        const int sa = (lane & 28) | (tig >> 1);
        const int sb = sa + 2;
        const bool odd = tig & 1;
#pragma unroll
        for (int j = 0; j < 8; j++) {
            float v0a = __shfl_sync(0xffffffffu, acc_s[j][0], sa);
            float v1a = __shfl_sync(0xffffffffu, acc_s[j][1], sa);
            float v2a = __shfl_sync(0xffffffffu, acc_s[j][2], sa);
            float v3a = __shfl_sync(0xffffffffu, acc_s[j][3], sa);
            float v0b = __shfl_sync(0xffffffffu, acc_s[j][0], sb);
            float v1b = __shfl_sync(0xffffffffu, acc_s[j][1], sb);
            float v2b = __shfl_sync(0xffffffffu, acc_s[j][2], sb);
            float v3b = __shfl_sync(0xffffffffu, acc_s[j][3], sb);
            acc_s[j][0] = to_tf32(odd ? v1a : v0a);
            acc_s[j][1] = to_tf32(odd ? v3a : v2a);
            acc_s[j][2] = to_tf32(odd ? v1b : v0b);
            acc_s[j][3] = to_tf32(odd ? v3b : v2b);
        }

        // ---- O += P @ V (V^T fragments via ldmatrix) ----
#pragma unroll
        for (int kc = 0; kc < 8; kc++) {
            uint32_t pa[4];
            pa[0] = __float_as_uint(acc_s[kc][0]);
            pa[1] = __float_as_uint(acc_s[kc][1]);
            pa[2] = __float_as_uint(acc_s[kc][2]);
            pa[3] = __float_as_uint(acc_s[kc][3]);
            uint32_t vb[4][4];
#pragma unroll
            for (int p = 0; p < 4; p++) ldsm4(vb[p], vf_addr[p] + kc * 32);
#pragma unroll
            for (int jd = 0; jd < 8; jd++)
                mma_tf32(acc_o[jd], pa, &vb[jd >> 1][(jd & 1) * 2]);
        }
        __syncthreads();
    }

    // ---- epilogue: O /= l ----
    const float inv0 = 1.f / l0, inv1 = 1.f / l1;
    float* ob = o + ((size_t)(b * SQ + gr0) * HDIM) + h * HSZ;
#pragma unroll
    for (int jd = 0; jd < 8; jd++) {
        const int c = jd * 8 + 2 * tig;
        *(float2*)(ob + c) = make_float2(acc_o[jd][0] * inv0, acc_o[jd][1] * inv0);
        *(float2*)(ob + (size_t)8 * HDIM + c) =
            make_float2(acc_o[jd][2] * inv1, acc_o[jd][3] * inv1);
    }
}

// ---------------------------------------------------------------------------
// LayerNorm over H=512, optional residual add. One block (256 thr) per row.
// ---------------------------------------------------------------------------
__global__ void __launch_bounds__(256)
ln_kernel(const float* __restrict__ y, const float* __restrict__ res,
          const float* __restrict__ g, const float* __restrict__ bta,
          float* __restrict__ out) {
    __shared__ float red[256];
    const int t = threadIdx.x;
    const size_t base = (size_t)blockIdx.x * HDIM;

    float v0 = y[base + t];
    float v1 = y[base + t + 256];
    if (res) {
        v0 += res[base + t];
        v1 += res[base + t + 256];
    }

    red[t] = v0 + v1;
    __syncthreads();
    for (int off = 128; off > 0; off >>= 1) {
        if (t < off) red[t] += red[t + off];
        __syncthreads();
    }
    const float mean = red[0] * (1.f / HDIM);
    __syncthreads();

    const float d0 = v0 - mean, d1 = v1 - mean;
    red[t] = d0 * d0 + d1 * d1;
    __syncthreads();
    for (int off = 128; off > 0; off >>= 1) {
        if (t < off) red[t] += red[t + off];
        __syncthreads();
    }
    const float rs = rsqrtf(red[0] * (1.f / HDIM) + EPSV);

    out[base + t]       = d0 * rs * g[t] + bta[t];
    out[base + t + 256] = d1 * rs * g[t + 256] + bta[t + 256];
}

// ---------------------------------------------------------------------------
// Final batch-norm over B=8 samples of x[:,0,:]. out[b,h].
// ---------------------------------------------------------------------------
__global__ void bn_kernel(const float* __restrict__ x, const float* __restrict__ g,
                          const float* __restrict__ bb, float* __restrict__ out) {
    const int h = blockIdx.x * blockDim.x + threadIdx.x;
    if (h >= HDIM) return;
    float v[NB];
    float m = 0.f;
#pragma unroll
    for (int b = 0; b < NB; b++) {
        v[b] = x[(size_t)b * SQ * HDIM + h];
        m += v[b];
    }
    m *= (1.f / NB);
    float var = 0.f;
#pragma unroll
    for (int b = 0; b < NB; b++) {
        float d = v[b] - m;
        var += d * d;
    }
    var *= (1.f / NB);
    const float rs = rsqrtf(var + EPSV);
#pragma unroll
    for (int b = 0; b < NB; b++)
        out[b * HDIM + h] = (v[b] - m) * rs * g[h] + bb[h];
}

// ---------------------------------------------------------------------------
// Launch
// ---------------------------------------------------------------------------
extern "C" void kernel_launch(void* const* d_in, const int* in_sizes, int n_in,
                              void* d_out, int out_size) {
    (void)in_sizes; (void)n_in; (void)out_size;

    const float* nodes      = (const float*)d_in[0];
    const int*   dist       = (const int*)d_in[1];
    const float* dense_w    = (const float*)d_in[2];
    const float* dense_b    = (const float*)d_in[3];
    const float* dense_ln_g = (const float*)d_in[4];
    const float* dense_ln_b = (const float*)d_in[5];
    const float* qkv_w      = (const float*)d_in[6];
    const float* qkv_b      = (const float*)d_in[7];
    const float* out_w      = (const float*)d_in[8];
    const float* out_b      = (const float*)d_in[9];
    const float* ln1_g      = (const float*)d_in[10];
    const float* ln1_b      = (const float*)d_in[11];
    const float* ffn_w1     = (const float*)d_in[12];
    const float* ffn_b1     = (const float*)d_in[13];
    const float* ffn_w2     = (const float*)d_in[14];
    const float* ffn_b2     = (const float*)d_in[15];
    const float* ln2_g      = (const float*)d_in[16];
    const float* ln2_b      = (const float*)d_in[17];
    const float* bn_g       = (const float*)d_in[18];
    const float* bn_b       = (const float*)d_in[19];
    float* out = (float*)d_out;

    float *xin, *x, *qkv, *o, *ffn, *tmp;
    cudaGetSymbolAddress((void**)&xin, g_xin);
    cudaGetSymbolAddress((void**)&x,   g_x);
    cudaGetSymbolAddress((void**)&qkv, g_qkv);
    cudaGetSymbolAddress((void**)&o,   g_o);
    cudaGetSymbolAddress((void**)&ffn, g_ffn);
    cudaGetSymbolAddress((void**)&tmp, g_tmp);

    const int M = NB * SQ;  // 8192 rows

    // input transpose + dense projection + LN
    transpose_nodes<<<(NB * SQ * ID + 255) / 256, 256>>>(nodes, xin);
    gemm_tn_tf32<<<dim3(HDIM / 128, M / 128), 256>>>(xin, ID, dense_w, ID, dense_b,
                                                     tmp, HDIM, ID, 0);
    ln_kernel<<<M, 256>>>(tmp, nullptr, dense_ln_g, dense_ln_b, x);

    for (int l = 0; l < NL; l++) {
        // QKV projection: [8192,512] @ [1536,512]^T
        gemm_tn_tf32<<<dim3(3 * HDIM / 128, M / 128), 256>>>(
            x, HDIM, qkv_w + (size_t)l * 3 * HDIM * HDIM, HDIM,
            qkv_b + l * 3 * HDIM, qkv, 3 * HDIM, HDIM, 0);

        // fused attention (scores + mask + softmax + AV)
        flash_attn<<<dim3(SQ / 128, NB * NHD), 256>>>(qkv, dist, o);

        // output projection + residual LN
        gemm_tn_tf32<<<dim3(HDIM / 128, M / 128), 256>>>(
            o, HDIM, out_w + (size_t)l * HDIM * HDIM, HDIM,
            out_b + l * HDIM, tmp, HDIM, HDIM, 0);
        ln_kernel<<<M, 256>>>(tmp, x, ln1_g + l * HDIM, ln1_b + l * HDIM, x);

        // FFN
        gemm_tn_tf32<<<dim3(FFD / 128, M / 128), 256>>>(
            x, HDIM, ffn_w1 + (size_t)l * FFD * HDIM, HDIM,
            ffn_b1 + l * FFD, ffn, FFD, HDIM, 1);
        gemm_tn_tf32<<<dim3(HDIM / 128, M / 128), 256>>>(
            ffn, FFD, ffn_w2 + (size_t)l * HDIM * FFD, FFD,
            ffn_b2 + l * HDIM, tmp, HDIM, FFD, 0);
        ln_kernel<<<M, 256>>>(tmp, x, ln2_g + l * HDIM, ln2_b + l * HDIM, x);
    }

    // final batch-norm over batch dim of x[:, 0, :]
    bn_kernel<<<1, HDIM>>>(x, bn_g, bn_b, out);
}